// round 1
// baseline (speedup 1.0000x reference)
#include <cuda_runtime.h>
#include <math.h>

#define BATCH 2
#define SEQ   2048
#define DMODEL 1024
#define NHEADS 16
#define HDIM  64
#define MTOT  (BATCH*SEQ)   // 4096

// Scratch (allocation-free rule: device globals)
__device__ float g_qp[MTOT*DMODEL];
__device__ float g_kp[MTOT*DMODEL];
__device__ float g_vp[MTOT*DMODEL];
__device__ float g_joint[MTOT*DMODEL];

// ---------------------------------------------------------------------------
// GEMM: out[m][n] = sum_k X[m][k] * W[n][k] + bias[n]
// X: [M, K=1024] row-major, W: [N=1024, K=1024] row-major (torch Linear weight)
// Tile: 64x64 output per CTA, BK=32, 256 threads, 4x4 per thread.
// ---------------------------------------------------------------------------
#define GBK 32
__global__ __launch_bounds__(256)
void gemm_bias_kernel(const float* __restrict__ X, const float* __restrict__ W,
                      const float* __restrict__ bias, float* __restrict__ out)
{
    __shared__ float Xs[64][GBK + 1];
    __shared__ float Ws[GBK][64 + 1];

    const int tid = threadIdx.x;
    const int tx = tid & 15;          // 0..15 -> 4 output cols each
    const int ty = tid >> 4;          // 0..15 -> 4 output rows each
    const int n0 = blockIdx.x * 64;
    const int m0 = blockIdx.y * 64;

    float acc[4][4] = {};

    for (int k0 = 0; k0 < DMODEL; k0 += GBK) {
        // Load X tile: 64x32 = 2048 elems, 8 per thread, coalesced along k
        #pragma unroll
        for (int i = 0; i < 8; i++) {
            int idx = i * 256 + tid;
            int r = idx >> 5, c = idx & 31;
            Xs[r][c] = X[(size_t)(m0 + r) * DMODEL + k0 + c];
        }
        // Load W tile transposed into Ws[k][n]: W[(n0+n)*K + k0+c]
        #pragma unroll
        for (int i = 0; i < 8; i++) {
            int idx = i * 256 + tid;
            int n = idx >> 5, c = idx & 31;
            Ws[c][n] = W[(size_t)(n0 + n) * DMODEL + k0 + c];
        }
        __syncthreads();

        #pragma unroll
        for (int kk = 0; kk < GBK; kk++) {
            float a[4], b[4];
            #pragma unroll
            for (int i = 0; i < 4; i++) a[i] = Xs[ty * 4 + i][kk];
            #pragma unroll
            for (int j = 0; j < 4; j++) b[j] = Ws[kk][tx * 4 + j];
            #pragma unroll
            for (int i = 0; i < 4; i++)
                #pragma unroll
                for (int j = 0; j < 4; j++)
                    acc[i][j] = fmaf(a[i], b[j], acc[i][j]);
        }
        __syncthreads();
    }

    #pragma unroll
    for (int i = 0; i < 4; i++) {
        size_t row = (size_t)(m0 + ty * 4 + i) * DMODEL;
        #pragma unroll
        for (int j = 0; j < 4; j++) {
            int col = n0 + tx * 4 + j;
            out[row + col] = acc[i][j] + bias[col];
        }
    }
}

// ---------------------------------------------------------------------------
// Flash-style attention. One CTA per (batch, head, 64-row Q tile).
// Online softmax; K/V tiles of 64 rows; mask from gmem.
// Dynamic smem: Qs/Ks/Vs/Ss each 64x65 floats + 3x64 row stats.
// ---------------------------------------------------------------------------
#define ATTN_SMEM_FLOATS (4 * 64 * 65 + 3 * 64)
#define ATTN_SMEM_BYTES  (ATTN_SMEM_FLOATS * 4)

__global__ __launch_bounds__(256)
void attn_kernel(const float* __restrict__ qp, const float* __restrict__ kp,
                 const float* __restrict__ vp, const int* __restrict__ mask,
                 float* __restrict__ joint)
{
    extern __shared__ float sm[];
    float* Qs  = sm;                    // [64][65]
    float* Ks  = Qs + 64 * 65;          // [64][65]
    float* Vs  = Ks + 64 * 65;          // [64][65]
    float* Ss  = Vs + 64 * 65;          // [64][65]
    float* m_s = Ss + 64 * 65;          // [64]
    float* l_s = m_s + 64;              // [64]
    float* a_s = l_s + 64;              // [64]

    const int tid = threadIdx.x;
    const int tx = tid & 15;
    const int ty = tid >> 4;
    const int b  = blockIdx.z;
    const int h  = blockIdx.y;
    const int q0 = blockIdx.x * 64;
    const float scale = 0.125f;   // 1/sqrt(64)

    // Load Q tile: Qs[r][d] = qp[b, q0+r, h*64+d]
    #pragma unroll
    for (int i = 0; i < 16; i++) {
        int idx = i * 256 + tid;
        int r = idx >> 6, d = idx & 63;
        Qs[r * 65 + d] = qp[((size_t)(b * SEQ + q0 + r)) * DMODEL + h * HDIM + d];
    }
    if (tid < 64) { m_s[tid] = -INFINITY; l_s[tid] = 0.0f; }

    float acc[4][4] = {};

    for (int k0 = 0; k0 < SEQ; k0 += 64) {
        __syncthreads();   // protect Ks/Vs reuse from previous iteration's PV reads

        // Load K and V tiles
        #pragma unroll
        for (int i = 0; i < 16; i++) {
            int idx = i * 256 + tid;
            int r = idx >> 6, d = idx & 63;
            size_t g = ((size_t)(b * SEQ + k0 + r)) * DMODEL + h * HDIM + d;
            Ks[r * 65 + d] = kp[g];
            Vs[r * 65 + d] = vp[g];
        }
        __syncthreads();

        // S = Q K^T  (64x64x64), 4x4 per thread
        float s[4][4] = {};
        #pragma unroll 8
        for (int d = 0; d < HDIM; d++) {
            float a[4], bb[4];
            #pragma unroll
            for (int i = 0; i < 4; i++) a[i] = Qs[(ty * 4 + i) * 65 + d];
            #pragma unroll
            for (int j = 0; j < 4; j++) bb[j] = Ks[(tx * 4 + j) * 65 + d];
            #pragma unroll
            for (int i = 0; i < 4; i++)
                #pragma unroll
                for (int j = 0; j < 4; j++)
                    s[i][j] = fmaf(a[i], bb[j], s[i][j]);
        }

        // Scale + mask -> smem
        #pragma unroll
        for (int i = 0; i < 4; i++) {
            int qr = q0 + ty * 4 + i;
            size_t mrow = ((size_t)b * SEQ + qr) * SEQ + k0;
            #pragma unroll
            for (int j = 0; j < 4; j++) {
                int kc = tx * 4 + j;
                int mv = mask[mrow + kc];
                Ss[(ty * 4 + i) * 65 + tx * 4 + j] =
                    (mv == 0) ? -1000000000.0f : s[i][j] * scale;
            }
        }
        __syncthreads();

        // Online softmax row update (thread t < 64 owns row t)
        if (tid < 64) {
            float mold = m_s[tid];
            float mx = mold;
            #pragma unroll 8
            for (int j = 0; j < 64; j++) mx = fmaxf(mx, Ss[tid * 65 + j]);
            float al = __expf(mold - mx);    // exp(-inf)=0 on first tile
            float sum = 0.0f;
            #pragma unroll 8
            for (int j = 0; j < 64; j++) {
                float p = __expf(Ss[tid * 65 + j] - mx);
                Ss[tid * 65 + j] = p;
                sum += p;
            }
            m_s[tid] = mx;
            l_s[tid] = l_s[tid] * al + sum;
            a_s[tid] = al;
        }
        __syncthreads();

        // Rescale accumulator and add P @ V
        #pragma unroll
        for (int i = 0; i < 4; i++) {
            float al = a_s[ty * 4 + i];
            #pragma unroll
            for (int j = 0; j < 4; j++) acc[i][j] *= al;
        }
        #pragma unroll 8
        for (int kk = 0; kk < 64; kk++) {
            float p[4], vv[4];
            #pragma unroll
            for (int i = 0; i < 4; i++) p[i] = Ss[(ty * 4 + i) * 65 + kk];
            #pragma unroll
            for (int j = 0; j < 4; j++) vv[j] = Vs[kk * 65 + tx * 4 + j];
            #pragma unroll
            for (int i = 0; i < 4; i++)
                #pragma unroll
                for (int j = 0; j < 4; j++)
                    acc[i][j] = fmaf(p[i], vv[j], acc[i][j]);
        }
    }

    // Epilogue: normalize and write joint[b, q, h*64 + d]
    #pragma unroll
    for (int i = 0; i < 4; i++) {
        float inv = 1.0f / l_s[ty * 4 + i];
        size_t row = ((size_t)(b * SEQ + q0 + ty * 4 + i)) * DMODEL + h * HDIM;
        #pragma unroll
        for (int j = 0; j < 4; j++)
            joint[row + tx * 4 + j] = acc[i][j] * inv;
    }
}

// ---------------------------------------------------------------------------
extern "C" void kernel_launch(void* const* d_in, const int* in_sizes, int n_in,
                              void* d_out, int out_size)
{
    const float* q    = (const float*)d_in[0];
    const float* k    = (const float*)d_in[1];
    const float* v    = (const float*)d_in[2];
    const int*   mask = (const int*)  d_in[3];
    const float* Wq   = (const float*)d_in[4];
    const float* bq   = (const float*)d_in[5];
    const float* Wk   = (const float*)d_in[6];
    const float* bk   = (const float*)d_in[7];
    const float* Wv   = (const float*)d_in[8];
    const float* bv   = (const float*)d_in[9];
    const float* Wo   = (const float*)d_in[10];
    const float* bo   = (const float*)d_in[11];
    float* out = (float*)d_out;

    void *p_qp, *p_kp, *p_vp, *p_joint;
    cudaGetSymbolAddress(&p_qp, g_qp);
    cudaGetSymbolAddress(&p_kp, g_kp);
    cudaGetSymbolAddress(&p_vp, g_vp);
    cudaGetSymbolAddress(&p_joint, g_joint);

    dim3 gemm_grid(DMODEL / 64, MTOT / 64);   // 16 x 64

    gemm_bias_kernel<<<gemm_grid, 256>>>(q, Wq, bq, (float*)p_qp);
    gemm_bias_kernel<<<gemm_grid, 256>>>(k, Wk, bk, (float*)p_kp);
    gemm_bias_kernel<<<gemm_grid, 256>>>(v, Wv, bv, (float*)p_vp);

    cudaFuncSetAttribute(attn_kernel,
                         cudaFuncAttributeMaxDynamicSharedMemorySize,
                         ATTN_SMEM_BYTES);
    dim3 attn_grid(SEQ / 64, NHEADS, BATCH);  // 32 x 16 x 2
    attn_kernel<<<attn_grid, 256, ATTN_SMEM_BYTES>>>(
        (const float*)p_qp, (const float*)p_kp, (const float*)p_vp, mask,
        (float*)p_joint);

    gemm_bias_kernel<<<gemm_grid, 256>>>((const float*)p_joint, Wo, bo, out);
}

// round 3
// speedup vs baseline: 1.5250x; 1.5250x over previous
#include <cuda_runtime.h>
#include <cuda_bf16.h>
#include <cstdint>
#include <math.h>

#define BATCH 2
#define SEQ   2048
#define DMODEL 1024
#define NHEADS 16
#define HDIM  64
#define MTOT  (BATCH*SEQ)   // 4096

// ---------------- scratch (allocation-free rule: device globals) -----------
__device__ float g_qp[MTOT*DMODEL];
__device__ float g_kp[MTOT*DMODEL];
__device__ float g_vp[MTOT*DMODEL];
__device__ float g_joint[MTOT*DMODEL];
__device__ __nv_bfloat16 g_ahi[MTOT*DMODEL];
__device__ __nv_bfloat16 g_alo[MTOT*DMODEL];
__device__ __nv_bfloat16 g_whi[DMODEL*DMODEL];
__device__ __nv_bfloat16 g_wlo[DMODEL*DMODEL];

// ---------------- helpers ---------------------------------------------------
__device__ __forceinline__ uint32_t smem_u32(const void* p) {
    uint32_t a;
    asm("{ .reg .u64 t; cvta.to.shared.u64 t, %1; cvt.u32.u64 %0, t; }"
        : "=r"(a) : "l"(p));
    return a;
}
__device__ __forceinline__ void cp16(uint32_t s, const void* g) {
    asm volatile("cp.async.cg.shared.global [%0], [%1], 16;" :: "r"(s), "l"(g));
}
#define CP_COMMIT()  asm volatile("cp.async.commit_group;" ::: "memory")
#define CP_WAIT(n)   asm volatile("cp.async.wait_group %0;" :: "n"(n) : "memory")

__device__ __forceinline__ void ldsm_x4(uint32_t* r, uint32_t addr) {
    asm volatile("ldmatrix.sync.aligned.m8n8.x4.shared.b16 {%0,%1,%2,%3}, [%4];"
                 : "=r"(r[0]), "=r"(r[1]), "=r"(r[2]), "=r"(r[3]) : "r"(addr));
}
__device__ __forceinline__ void mma16816(float* d, const uint32_t* a,
                                         const uint32_t* b) {
    asm volatile(
        "mma.sync.aligned.m16n8k16.row.col.f32.bf16.bf16.f32 "
        "{%0,%1,%2,%3}, {%4,%5,%6,%7}, {%8,%9}, {%0,%1,%2,%3};"
        : "+f"(d[0]), "+f"(d[1]), "+f"(d[2]), "+f"(d[3])
        : "r"(a[0]), "r"(a[1]), "r"(a[2]), "r"(a[3]), "r"(b[0]), "r"(b[1]));
}

// ---------------------------------------------------------------------------
// split fp32 -> (bf16 hi, bf16 lo)
// ---------------------------------------------------------------------------
__global__ __launch_bounds__(256)
void split_kernel(const float4* __restrict__ x, __nv_bfloat162* __restrict__ hi,
                  __nv_bfloat162* __restrict__ lo, int n4)
{
    int i = blockIdx.x * 256 + threadIdx.x;
    if (i >= n4) return;
    float4 v = x[i];
    __nv_bfloat16 h0 = __float2bfloat16_rn(v.x);
    __nv_bfloat16 h1 = __float2bfloat16_rn(v.y);
    __nv_bfloat16 h2 = __float2bfloat16_rn(v.z);
    __nv_bfloat16 h3 = __float2bfloat16_rn(v.w);
    __nv_bfloat16 l0 = __float2bfloat16_rn(v.x - __bfloat162float(h0));
    __nv_bfloat16 l1 = __float2bfloat16_rn(v.y - __bfloat162float(h1));
    __nv_bfloat16 l2 = __float2bfloat16_rn(v.z - __bfloat162float(h2));
    __nv_bfloat16 l3 = __float2bfloat16_rn(v.w - __bfloat162float(h3));
    hi[2*i]   = __halves2bfloat162(h0, h1);
    hi[2*i+1] = __halves2bfloat162(h2, h3);
    lo[2*i]   = __halves2bfloat162(l0, l1);
    lo[2*i+1] = __halves2bfloat162(l2, l3);
}

// ---------------------------------------------------------------------------
// mma.sync bf16 GEMM: out[m][n] = sum_k A[m][k]*W[n][k] + bias[n]
// split-bf16: out = Ah*Wh + Ah*Wl + Al*Wh (fp32 accumulate)
// CTA tile 128x128, BK=32, 8 warps (warp tile 32x64), 2-stage cp.async.
// smem rows padded to 40 bf16 (80B) -> conflict-free ldmatrix.
// ---------------------------------------------------------------------------
#define BM 128
#define BN 128
#define BK 32
#define NCHUNK (DMODEL / BK)        // 32
#define ROWB 80                     // padded row bytes (40 bf16)
#define MAT_B (128 * ROWB)          // 10240 per matrix tile
#define OFF_AH 0
#define OFF_AL (1 * MAT_B)
#define OFF_BH (2 * MAT_B)
#define OFF_BL (3 * MAT_B)
#define STAGE_B (4 * MAT_B)         // 40960
#define GEMM_SMEM (2 * STAGE_B)     // 81920

__global__ __launch_bounds__(256)
void gemm_mma_kernel(const __nv_bfloat16* __restrict__ Ahi,
                     const __nv_bfloat16* __restrict__ Alo,
                     const __nv_bfloat16* __restrict__ Bhi,
                     const __nv_bfloat16* __restrict__ Blo,
                     const float* __restrict__ bias, float* __restrict__ out)
{
    extern __shared__ char smraw[];
    const uint32_t sbase = smem_u32(smraw);
    const int tid  = threadIdx.x;
    const int lane = tid & 31;
    const int wid  = tid >> 5;
    const int wm   = (wid & 3) * 32;     // warp m offset within CTA
    const int wn   = (wid >> 2) * 64;    // warp n offset within CTA
    const int n0   = blockIdx.x * BN;
    const int m0   = blockIdx.y * BM;

    float c[2][8][4];
    #pragma unroll
    for (int mt = 0; mt < 2; mt++)
        #pragma unroll
        for (int nt = 0; nt < 8; nt++)
            #pragma unroll
            for (int j = 0; j < 4; j++) c[mt][nt][j] = 0.0f;

    auto load_chunk = [&](int ck, int s) {
        uint32_t st = sbase + s * STAGE_B;
        int k0 = ck * BK;
        #pragma unroll
        for (int u = tid; u < 512; u += 256) {     // A: 128 rows x 4 chunks
            int r = u >> 2, c16 = u & 3;
            uint32_t d = st + r * ROWB + c16 * 16;
            size_t g = (size_t)(m0 + r) * DMODEL + k0 + c16 * 8;
            cp16(d + OFF_AH, Ahi + g);
            cp16(d + OFF_AL, Alo + g);
        }
        #pragma unroll
        for (int u = tid; u < 512; u += 256) {     // B: 128 rows x 4 chunks
            int r = u >> 2, c16 = u & 3;
            uint32_t d = st + r * ROWB + c16 * 16;
            size_t g = (size_t)(n0 + r) * DMODEL + k0 + c16 * 8;
            cp16(d + OFF_BH, Bhi + g);
            cp16(d + OFF_BL, Blo + g);
        }
    };

    load_chunk(0, 0); CP_COMMIT();

    // per-lane ldmatrix address components
    const int a_row  = lane & 15;            // row within m16 tile
    const int a_kb   = ((lane >> 4) & 1) * 16;  // 8 bf16 = 16 bytes
    const int b_row  = (lane & 7) + ((lane >> 4) & 1) * 8;
    const int b_kb   = ((lane >> 3) & 1) * 16;

    for (int ck = 0; ck < NCHUNK; ck++) {
        int s = ck & 1;
        if (ck + 1 < NCHUNK) {
            load_chunk(ck + 1, s ^ 1); CP_COMMIT();
            CP_WAIT(1);
        } else {
            CP_WAIT(0);
        }
        __syncthreads();

        uint32_t st = sbase + s * STAGE_B;
        #pragma unroll
        for (int ks = 0; ks < 2; ks++) {
            int kb = ks * 32;   // 16 bf16 per k-step = 32 bytes
            uint32_t ah[2][4], al[2][4];
            #pragma unroll
            for (int mt = 0; mt < 2; mt++) {
                uint32_t addr = st + (wm + mt * 16 + a_row) * ROWB + kb + a_kb;
                ldsm_x4(ah[mt], addr + OFF_AH);
                ldsm_x4(al[mt], addr + OFF_AL);
            }
            #pragma unroll
            for (int np = 0; np < 4; np++) {
                uint32_t bh4[4], bl4[4];
                uint32_t addr = st + (wn + np * 16 + b_row) * ROWB + kb + b_kb;
                ldsm_x4(bh4, addr + OFF_BH);
                ldsm_x4(bl4, addr + OFF_BL);
                #pragma unroll
                for (int mt = 0; mt < 2; mt++) {
                    mma16816(c[mt][np*2],   ah[mt], bh4);
                    mma16816(c[mt][np*2],   ah[mt], bl4);
                    mma16816(c[mt][np*2],   al[mt], bh4);
                    mma16816(c[mt][np*2+1], ah[mt], bh4 + 2);
                    mma16816(c[mt][np*2+1], ah[mt], bl4 + 2);
                    mma16816(c[mt][np*2+1], al[mt], bh4 + 2);
                }
            }
        }
        __syncthreads();
    }

    // epilogue: c frag lane mapping: rows g=lane>>2 (+8), cols (lane&3)*2 (+1)
    const int g  = lane >> 2;
    const int cq = (lane & 3) * 2;
    #pragma unroll
    for (int mt = 0; mt < 2; mt++) {
        #pragma unroll
        for (int nt = 0; nt < 8; nt++) {
            int col = n0 + wn + nt * 8 + cq;
            float2 bv = *(const float2*)(bias + col);
            int r0 = m0 + wm + mt * 16 + g;
            float2 o0 = make_float2(c[mt][nt][0] + bv.x, c[mt][nt][1] + bv.y);
            float2 o1 = make_float2(c[mt][nt][2] + bv.x, c[mt][nt][3] + bv.y);
            *(float2*)(out + (size_t)r0 * DMODEL + col) = o0;
            *(float2*)(out + (size_t)(r0 + 8) * DMODEL + col) = o1;
        }
    }
}

// ---------------------------------------------------------------------------
// Flash-style FP32 attention (validated in R1).
// ---------------------------------------------------------------------------
#define ATTN_SMEM_FLOATS (4 * 64 * 65 + 3 * 64)
#define ATTN_SMEM_BYTES  (ATTN_SMEM_FLOATS * 4)

__global__ __launch_bounds__(256)
void attn_kernel(const float* __restrict__ qp, const float* __restrict__ kp,
                 const float* __restrict__ vp, const int* __restrict__ mask,
                 float* __restrict__ joint)
{
    extern __shared__ float smf[];
    float* Qs  = smf;
    float* Ks  = Qs + 64 * 65;
    float* Vs  = Ks + 64 * 65;
    float* Ss  = Vs + 64 * 65;
    float* m_s = Ss + 64 * 65;
    float* l_s = m_s + 64;
    float* a_s = l_s + 64;

    const int tid = threadIdx.x;
    const int tx = tid & 15;
    const int ty = tid >> 4;
    const int b  = blockIdx.z;
    const int h  = blockIdx.y;
    const int q0 = blockIdx.x * 64;
    const float scale = 0.125f;

    #pragma unroll
    for (int i = 0; i < 16; i++) {
        int idx = i * 256 + tid;
        int r = idx >> 6, d = idx & 63;
        Qs[r * 65 + d] = qp[((size_t)(b * SEQ + q0 + r)) * DMODEL + h * HDIM + d];
    }
    if (tid < 64) { m_s[tid] = -INFINITY; l_s[tid] = 0.0f; }

    float acc[4][4] = {};

    for (int k0 = 0; k0 < SEQ; k0 += 64) {
        __syncthreads();
        #pragma unroll
        for (int i = 0; i < 16; i++) {
            int idx = i * 256 + tid;
            int r = idx >> 6, d = idx & 63;
            size_t gidx = ((size_t)(b * SEQ + k0 + r)) * DMODEL + h * HDIM + d;
            Ks[r * 65 + d] = kp[gidx];
            Vs[r * 65 + d] = vp[gidx];
        }
        __syncthreads();

        float s[4][4] = {};
        #pragma unroll 8
        for (int d = 0; d < HDIM; d++) {
            float a[4], bb[4];
            #pragma unroll
            for (int i = 0; i < 4; i++) a[i] = Qs[(ty * 4 + i) * 65 + d];
            #pragma unroll
            for (int j = 0; j < 4; j++) bb[j] = Ks[(tx * 4 + j) * 65 + d];
            #pragma unroll
            for (int i = 0; i < 4; i++)
                #pragma unroll
                for (int j = 0; j < 4; j++)
                    s[i][j] = fmaf(a[i], bb[j], s[i][j]);
        }

        #pragma unroll
        for (int i = 0; i < 4; i++) {
            int qr = q0 + ty * 4 + i;
            size_t mrow = ((size_t)b * SEQ + qr) * SEQ + k0;
            #pragma unroll
            for (int j = 0; j < 4; j++) {
                int kc = tx * 4 + j;
                int mv = mask[mrow + kc];
                Ss[(ty * 4 + i) * 65 + tx * 4 + j] =
                    (mv == 0) ? -1000000000.0f : s[i][j] * scale;
            }
        }
        __syncthreads();

        if (tid < 64) {
            float mold = m_s[tid];
            float mx = mold;
            #pragma unroll 8
            for (int j = 0; j < 64; j++) mx = fmaxf(mx, Ss[tid * 65 + j]);
            float al = __expf(mold - mx);
            float sum = 0.0f;
            #pragma unroll 8
            for (int j = 0; j < 64; j++) {
                float p = __expf(Ss[tid * 65 + j] - mx);
                Ss[tid * 65 + j] = p;
                sum += p;
            }
            m_s[tid] = mx;
            l_s[tid] = l_s[tid] * al + sum;
            a_s[tid] = al;
        }
        __syncthreads();

        #pragma unroll
        for (int i = 0; i < 4; i++) {
            float al = a_s[ty * 4 + i];
            #pragma unroll
            for (int j = 0; j < 4; j++) acc[i][j] *= al;
        }
        #pragma unroll 8
        for (int kk = 0; kk < 64; kk++) {
            float p[4], vv[4];
            #pragma unroll
            for (int i = 0; i < 4; i++) p[i] = Ss[(ty * 4 + i) * 65 + kk];
            #pragma unroll
            for (int j = 0; j < 4; j++) vv[j] = Vs[kk * 65 + tx * 4 + j];
            #pragma unroll
            for (int i = 0; i < 4; i++)
                #pragma unroll
                for (int j = 0; j < 4; j++)
                    acc[i][j] = fmaf(p[i], vv[j], acc[i][j]);
        }
    }

    #pragma unroll
    for (int i = 0; i < 4; i++) {
        float inv = 1.0f / l_s[ty * 4 + i];
        size_t row = ((size_t)(b * SEQ + q0 + ty * 4 + i)) * DMODEL + h * HDIM;
        #pragma unroll
        for (int j = 0; j < 4; j++)
            joint[row + tx * 4 + j] = acc[i][j] * inv;
    }
}

// ---------------------------------------------------------------------------
extern "C" void kernel_launch(void* const* d_in, const int* in_sizes, int n_in,
                              void* d_out, int out_size)
{
    const float* q    = (const float*)d_in[0];
    const float* k    = (const float*)d_in[1];
    const float* v    = (const float*)d_in[2];
    const int*   mask = (const int*)  d_in[3];
    const float* Wq   = (const float*)d_in[4];
    const float* bq   = (const float*)d_in[5];
    const float* Wk   = (const float*)d_in[6];
    const float* bk   = (const float*)d_in[7];
    const float* Wv   = (const float*)d_in[8];
    const float* bv   = (const float*)d_in[9];
    const float* Wo   = (const float*)d_in[10];
    const float* bo   = (const float*)d_in[11];
    float* out = (float*)d_out;

    void *p_qp, *p_kp, *p_vp, *p_joint, *p_ahi, *p_alo, *p_whi, *p_wlo;
    cudaGetSymbolAddress(&p_qp, g_qp);
    cudaGetSymbolAddress(&p_kp, g_kp);
    cudaGetSymbolAddress(&p_vp, g_vp);
    cudaGetSymbolAddress(&p_joint, g_joint);
    cudaGetSymbolAddress(&p_ahi, g_ahi);
    cudaGetSymbolAddress(&p_alo, g_alo);
    cudaGetSymbolAddress(&p_whi, g_whi);
    cudaGetSymbolAddress(&p_wlo, g_wlo);

    __nv_bfloat16* ahi = (__nv_bfloat16*)p_ahi;
    __nv_bfloat16* alo = (__nv_bfloat16*)p_alo;
    __nv_bfloat16* whi = (__nv_bfloat16*)p_whi;
    __nv_bfloat16* wlo = (__nv_bfloat16*)p_wlo;

    const int nX4 = MTOT * DMODEL / 4;
    const int nW4 = DMODEL * DMODEL / 4;

    cudaFuncSetAttribute(gemm_mma_kernel,
                         cudaFuncAttributeMaxDynamicSharedMemorySize, GEMM_SMEM);
    cudaFuncSetAttribute(attn_kernel,
                         cudaFuncAttributeMaxDynamicSharedMemorySize, ATTN_SMEM_BYTES);

    dim3 gg(DMODEL / BN, MTOT / BM);       // 8 x 32

    // Q projection
    split_kernel<<<nX4 / 256, 256>>>((const float4*)q, (__nv_bfloat162*)ahi, (__nv_bfloat162*)alo, nX4);
    split_kernel<<<nW4 / 256, 256>>>((const float4*)Wq, (__nv_bfloat162*)whi, (__nv_bfloat162*)wlo, nW4);
    gemm_mma_kernel<<<gg, 256, GEMM_SMEM>>>(ahi, alo, whi, wlo, bq, (float*)p_qp);

    // K projection
    split_kernel<<<nX4 / 256, 256>>>((const float4*)k, (__nv_bfloat162*)ahi, (__nv_bfloat162*)alo, nX4);
    split_kernel<<<nW4 / 256, 256>>>((const float4*)Wk, (__nv_bfloat162*)whi, (__nv_bfloat162*)wlo, nW4);
    gemm_mma_kernel<<<gg, 256, GEMM_SMEM>>>(ahi, alo, whi, wlo, bk, (float*)p_kp);

    // V projection
    split_kernel<<<nX4 / 256, 256>>>((const float4*)v, (__nv_bfloat162*)ahi, (__nv_bfloat162*)alo, nX4);
    split_kernel<<<nW4 / 256, 256>>>((const float4*)Wv, (__nv_bfloat162*)whi, (__nv_bfloat162*)wlo, nW4);
    gemm_mma_kernel<<<gg, 256, GEMM_SMEM>>>(ahi, alo, whi, wlo, bv, (float*)p_vp);

    // attention
    dim3 ag(SEQ / 64, NHEADS, BATCH);
    attn_kernel<<<ag, 256, ATTN_SMEM_BYTES>>>(
        (const float*)p_qp, (const float*)p_kp, (const float*)p_vp, mask,
        (float*)p_joint);

    // output projection
    split_kernel<<<nX4 / 256, 256>>>((const float4*)p_joint, (__nv_bfloat162*)ahi, (__nv_bfloat162*)alo, nX4);
    split_kernel<<<nW4 / 256, 256>>>((const float4*)Wo, (__nv_bfloat162*)whi, (__nv_bfloat162*)wlo, nW4);
    gemm_mma_kernel<<<gg, 256, GEMM_SMEM>>>(ahi, alo, whi, wlo, bo, out);
}

// round 4
// speedup vs baseline: 2.9699x; 1.9475x over previous
#include <cuda_runtime.h>
#include <cuda_bf16.h>
#include <cstdint>
#include <math.h>

#define BATCH 2
#define SEQ   2048
#define DMODEL 1024
#define NHEADS 16
#define HDIM  64
#define MTOT  (BATCH*SEQ)   // 4096

// ---------------- scratch (allocation-free rule: device globals) -----------
__device__ float g_qp[MTOT*DMODEL];
__device__ float g_kp[MTOT*DMODEL];
__device__ float g_vp[MTOT*DMODEL];
__device__ float g_joint[MTOT*DMODEL];
__device__ __nv_bfloat16 g_ahi[MTOT*DMODEL];
__device__ __nv_bfloat16 g_alo[MTOT*DMODEL];
__device__ __nv_bfloat16 g_whi[DMODEL*DMODEL];
__device__ __nv_bfloat16 g_wlo[DMODEL*DMODEL];
__device__ __nv_bfloat16 g_qhi[MTOT*DMODEL];
__device__ __nv_bfloat16 g_qlo[MTOT*DMODEL];
__device__ __nv_bfloat16 g_khi[MTOT*DMODEL];
__device__ __nv_bfloat16 g_klo[MTOT*DMODEL];
__device__ __nv_bfloat16 g_vhi[MTOT*DMODEL];
__device__ __nv_bfloat16 g_vlo[MTOT*DMODEL];

// ---------------- helpers ---------------------------------------------------
__device__ __forceinline__ uint32_t smem_u32(const void* p) {
    uint32_t a;
    asm("{ .reg .u64 t; cvta.to.shared.u64 t, %1; cvt.u32.u64 %0, t; }"
        : "=r"(a) : "l"(p));
    return a;
}
__device__ __forceinline__ void cp16(uint32_t s, const void* g) {
    asm volatile("cp.async.cg.shared.global [%0], [%1], 16;" :: "r"(s), "l"(g));
}
#define CP_COMMIT()  asm volatile("cp.async.commit_group;" ::: "memory")
#define CP_WAIT(n)   asm volatile("cp.async.wait_group %0;" :: "n"(n) : "memory")

__device__ __forceinline__ void ldsm_x4(uint32_t* r, uint32_t addr) {
    asm volatile("ldmatrix.sync.aligned.m8n8.x4.shared.b16 {%0,%1,%2,%3}, [%4];"
                 : "=r"(r[0]), "=r"(r[1]), "=r"(r[2]), "=r"(r[3]) : "r"(addr));
}
__device__ __forceinline__ void ldsm_x4_t(uint32_t* r, uint32_t addr) {
    asm volatile("ldmatrix.sync.aligned.m8n8.x4.trans.shared.b16 {%0,%1,%2,%3}, [%4];"
                 : "=r"(r[0]), "=r"(r[1]), "=r"(r[2]), "=r"(r[3]) : "r"(addr));
}
__device__ __forceinline__ void mma16816(float* d, const uint32_t* a,
                                         const uint32_t* b) {
    asm volatile(
        "mma.sync.aligned.m16n8k16.row.col.f32.bf16.bf16.f32 "
        "{%0,%1,%2,%3}, {%4,%5,%6,%7}, {%8,%9}, {%0,%1,%2,%3};"
        : "+f"(d[0]), "+f"(d[1]), "+f"(d[2]), "+f"(d[3])
        : "r"(a[0]), "r"(a[1]), "r"(a[2]), "r"(a[3]), "r"(b[0]), "r"(b[1]));
}
// pack (x,y) to bf16x2 hi plus residual lo
__device__ __forceinline__ void pack_split(float x, float y,
                                           uint32_t& hi, uint32_t& lo) {
    uint32_t h;
    asm("cvt.rn.bf16x2.f32 %0, %1, %2;" : "=r"(h) : "f"(y), "f"(x));
    float hx = __uint_as_float(h << 16);
    float hy = __uint_as_float(h & 0xffff0000u);
    float lx = x - hx, ly = y - hy;
    uint32_t l;
    asm("cvt.rn.bf16x2.f32 %0, %1, %2;" : "=r"(l) : "f"(ly), "f"(lx));
    hi = h; lo = l;
}

// ---------------------------------------------------------------------------
// split fp32 -> (bf16 hi, bf16 lo), optional scale
// ---------------------------------------------------------------------------
__global__ __launch_bounds__(256)
void split_kernel(const float4* __restrict__ x, __nv_bfloat162* __restrict__ hi,
                  __nv_bfloat162* __restrict__ lo, int n4, float scale)
{
    int i = blockIdx.x * 256 + threadIdx.x;
    if (i >= n4) return;
    float4 v = x[i];
    v.x *= scale; v.y *= scale; v.z *= scale; v.w *= scale;
    __nv_bfloat16 h0 = __float2bfloat16_rn(v.x);
    __nv_bfloat16 h1 = __float2bfloat16_rn(v.y);
    __nv_bfloat16 h2 = __float2bfloat16_rn(v.z);
    __nv_bfloat16 h3 = __float2bfloat16_rn(v.w);
    __nv_bfloat16 l0 = __float2bfloat16_rn(v.x - __bfloat162float(h0));
    __nv_bfloat16 l1 = __float2bfloat16_rn(v.y - __bfloat162float(h1));
    __nv_bfloat16 l2 = __float2bfloat16_rn(v.z - __bfloat162float(h2));
    __nv_bfloat16 l3 = __float2bfloat16_rn(v.w - __bfloat162float(h3));
    hi[2*i]   = __halves2bfloat162(h0, h1);
    hi[2*i+1] = __halves2bfloat162(h2, h3);
    lo[2*i]   = __halves2bfloat162(l0, l1);
    lo[2*i+1] = __halves2bfloat162(l2, l3);
}

// ---------------------------------------------------------------------------
// mma.sync bf16 GEMM (validated R3): out = A*W^T + bias, split-bf16 3-MMA.
// ---------------------------------------------------------------------------
#define BM 128
#define BN 128
#define BK 32
#define NCHUNK (DMODEL / BK)
#define ROWB 80
#define MAT_B (128 * ROWB)
#define OFF_AH 0
#define OFF_AL (1 * MAT_B)
#define OFF_BH (2 * MAT_B)
#define OFF_BL (3 * MAT_B)
#define STAGE_B (4 * MAT_B)
#define GEMM_SMEM (2 * STAGE_B)

__global__ __launch_bounds__(256)
void gemm_mma_kernel(const __nv_bfloat16* __restrict__ Ahi,
                     const __nv_bfloat16* __restrict__ Alo,
                     const __nv_bfloat16* __restrict__ Bhi,
                     const __nv_bfloat16* __restrict__ Blo,
                     const float* __restrict__ bias, float* __restrict__ out)
{
    extern __shared__ char smraw[];
    const uint32_t sbase = smem_u32(smraw);
    const int tid  = threadIdx.x;
    const int lane = tid & 31;
    const int wid  = tid >> 5;
    const int wm   = (wid & 3) * 32;
    const int wn   = (wid >> 2) * 64;
    const int n0   = blockIdx.x * BN;
    const int m0   = blockIdx.y * BM;

    float c[2][8][4];
    #pragma unroll
    for (int mt = 0; mt < 2; mt++)
        #pragma unroll
        for (int nt = 0; nt < 8; nt++)
            #pragma unroll
            for (int j = 0; j < 4; j++) c[mt][nt][j] = 0.0f;

    auto load_chunk = [&](int ck, int s) {
        uint32_t st = sbase + s * STAGE_B;
        int k0 = ck * BK;
        #pragma unroll
        for (int u = tid; u < 512; u += 256) {
            int r = u >> 2, c16 = u & 3;
            uint32_t d = st + r * ROWB + c16 * 16;
            size_t g = (size_t)(m0 + r) * DMODEL + k0 + c16 * 8;
            cp16(d + OFF_AH, Ahi + g);
            cp16(d + OFF_AL, Alo + g);
        }
        #pragma unroll
        for (int u = tid; u < 512; u += 256) {
            int r = u >> 2, c16 = u & 3;
            uint32_t d = st + r * ROWB + c16 * 16;
            size_t g = (size_t)(n0 + r) * DMODEL + k0 + c16 * 8;
            cp16(d + OFF_BH, Bhi + g);
            cp16(d + OFF_BL, Blo + g);
        }
    };

    load_chunk(0, 0); CP_COMMIT();

    const int a_row  = lane & 15;
    const int a_kb   = ((lane >> 4) & 1) * 16;
    const int b_row  = (lane & 7) + ((lane >> 4) & 1) * 8;
    const int b_kb   = ((lane >> 3) & 1) * 16;

    for (int ck = 0; ck < NCHUNK; ck++) {
        int s = ck & 1;
        if (ck + 1 < NCHUNK) {
            load_chunk(ck + 1, s ^ 1); CP_COMMIT();
            CP_WAIT(1);
        } else {
            CP_WAIT(0);
        }
        __syncthreads();

        uint32_t st = sbase + s * STAGE_B;
        #pragma unroll
        for (int ks = 0; ks < 2; ks++) {
            int kb = ks * 32;
            uint32_t ah[2][4], al[2][4];
            #pragma unroll
            for (int mt = 0; mt < 2; mt++) {
                uint32_t addr = st + (wm + mt * 16 + a_row) * ROWB + kb + a_kb;
                ldsm_x4(ah[mt], addr + OFF_AH);
                ldsm_x4(al[mt], addr + OFF_AL);
            }
            #pragma unroll
            for (int np = 0; np < 4; np++) {
                uint32_t bh4[4], bl4[4];
                uint32_t addr = st + (wn + np * 16 + b_row) * ROWB + kb + b_kb;
                ldsm_x4(bh4, addr + OFF_BH);
                ldsm_x4(bl4, addr + OFF_BL);
                #pragma unroll
                for (int mt = 0; mt < 2; mt++) {
                    mma16816(c[mt][np*2],   ah[mt], bh4);
                    mma16816(c[mt][np*2],   ah[mt], bl4);
                    mma16816(c[mt][np*2],   al[mt], bh4);
                    mma16816(c[mt][np*2+1], ah[mt], bh4 + 2);
                    mma16816(c[mt][np*2+1], ah[mt], bl4 + 2);
                    mma16816(c[mt][np*2+1], al[mt], bh4 + 2);
                }
            }
        }
        __syncthreads();
    }

    const int g  = lane >> 2;
    const int cq = (lane & 3) * 2;
    #pragma unroll
    for (int mt = 0; mt < 2; mt++) {
        #pragma unroll
        for (int nt = 0; nt < 8; nt++) {
            int col = n0 + wn + nt * 8 + cq;
            float2 bv = *(const float2*)(bias + col);
            int r0 = m0 + wm + mt * 16 + g;
            float2 o0 = make_float2(c[mt][nt][0] + bv.x, c[mt][nt][1] + bv.y);
            float2 o1 = make_float2(c[mt][nt][2] + bv.x, c[mt][nt][3] + bv.y);
            *(float2*)(out + (size_t)r0 * DMODEL + col) = o0;
            *(float2*)(out + (size_t)(r0 + 8) * DMODEL + col) = o1;
        }
    }
}

// ---------------------------------------------------------------------------
// FA2-style mma.sync attention, split-bf16 for QK^T and PV.
// CTA: 128 Q rows for one (b,h); 8 warps, each warp m16.
// K/V tiles of 64 seq rows, double-buffered cp.async.
// smem rows = 64 bf16 (128B) padded to 144B.
// ---------------------------------------------------------------------------
#define AROWB 144
#define AQ_B   (128 * AROWB)      // 18432
#define AKV_B  (64 * AROWB)       // 9216
#define A_OFF_QH 0
#define A_OFF_QL AQ_B
#define A_STAGE0 (2 * AQ_B)       // 36864
#define A_STAGE_B (4 * AKV_B)     // 36864
#define A_OFF_KH 0
#define A_OFF_KL AKV_B
#define A_OFF_VH (2 * AKV_B)
#define A_OFF_VL (3 * AKV_B)
#define ATTN_SMEM (A_STAGE0 + 2 * A_STAGE_B)   // 110592

__global__ __launch_bounds__(256, 1)
void attn_mma_kernel(const __nv_bfloat16* __restrict__ qhi,
                     const __nv_bfloat16* __restrict__ qlo,
                     const __nv_bfloat16* __restrict__ khi,
                     const __nv_bfloat16* __restrict__ klo,
                     const __nv_bfloat16* __restrict__ vhi,
                     const __nv_bfloat16* __restrict__ vlo,
                     const int* __restrict__ mask,
                     float* __restrict__ joint)
{
    extern __shared__ char smraw[];
    const uint32_t sbase = smem_u32(smraw);
    const int tid  = threadIdx.x;
    const int lane = tid & 31;
    const int wid  = tid >> 5;
    const int wm   = wid * 16;
    const int b    = blockIdx.z;
    const int h    = blockIdx.y;
    const int q0   = blockIdx.x * 128;

    // ---- load Q tile (hi/lo), 128 rows x 64 bf16 ----
    #pragma unroll
    for (int u = tid; u < 1024; u += 256) {
        int r = u >> 3, c16 = u & 7;
        uint32_t d = sbase + r * AROWB + c16 * 16;
        size_t g = ((size_t)(b * SEQ + q0 + r)) * DMODEL + h * HDIM + c16 * 8;
        cp16(d + A_OFF_QH, qhi + g);
        cp16(d + A_OFF_QL, qlo + g);
    }
    CP_COMMIT(); CP_WAIT(0);
    __syncthreads();

    // ---- preload Q fragments (4 k16 chunks, hi/lo) ----
    uint32_t aqh[4][4], aql[4][4];
    {
        const int a_row = lane & 15;
        const int a_kb  = ((lane >> 4) & 1) * 16;
        #pragma unroll
        for (int kc = 0; kc < 4; kc++) {
            uint32_t addr = sbase + (wm + a_row) * AROWB + kc * 32 + a_kb;
            ldsm_x4(aqh[kc], addr + A_OFF_QH);
            ldsm_x4(aql[kc], addr + A_OFF_QL);
        }
    }

    const int g_   = lane >> 2;
    const int cq   = (lane & 3) * 2;
    const int b_row = (lane & 7) + ((lane >> 4) & 1) * 8;
    const int b_kb  = ((lane >> 3) & 1) * 16;
    const int v_row = lane & 15;
    const int v_col = (lane >> 4) * 8;

    const size_t mrow0 = ((size_t)b * SEQ + q0 + wm + g_) * SEQ;
    const size_t mrow1 = mrow0 + (size_t)8 * SEQ;

    float o[8][4];
    #pragma unroll
    for (int i = 0; i < 8; i++)
        #pragma unroll
        for (int j = 0; j < 4; j++) o[i][j] = 0.0f;
    float m0r = -INFINITY, m1r = -INFINITY, l0r = 0.0f, l1r = 0.0f;

    auto load_kv = [&](int kt, int s) {
        uint32_t st = sbase + A_STAGE0 + s * A_STAGE_B;
        int k0 = kt * 64;
        #pragma unroll
        for (int u = tid; u < 512; u += 256) {
            int r = u >> 3, c16 = u & 7;
            uint32_t d = st + r * AROWB + c16 * 16;
            size_t g = ((size_t)(b * SEQ + k0 + r)) * DMODEL + h * HDIM + c16 * 8;
            cp16(d + A_OFF_KH, khi + g);
            cp16(d + A_OFF_KL, klo + g);
            cp16(d + A_OFF_VH, vhi + g);
            cp16(d + A_OFF_VL, vlo + g);
        }
    };

    load_kv(0, 0); CP_COMMIT();

    for (int kt = 0; kt < SEQ / 64; kt++) {
        int s = kt & 1;
        __syncthreads();   // all warps done with buffer s^1 before refill
        if (kt + 1 < SEQ / 64) {
            load_kv(kt + 1, s ^ 1); CP_COMMIT();
            CP_WAIT(1);
        } else {
            CP_WAIT(0);
        }
        __syncthreads();

        uint32_t st = sbase + A_STAGE0 + s * A_STAGE_B;
        int k0 = kt * 64;

        // ---- S = Q K^T (split-bf16, 3 MMAs) ----
        float sc[8][4];
        #pragma unroll
        for (int i = 0; i < 8; i++)
            #pragma unroll
            for (int j = 0; j < 4; j++) sc[i][j] = 0.0f;

        #pragma unroll
        for (int kc = 0; kc < 4; kc++) {
            #pragma unroll
            for (int np = 0; np < 4; np++) {
                uint32_t bh4[4], bl4[4];
                uint32_t addr = st + (np * 16 + b_row) * AROWB + kc * 32 + b_kb;
                ldsm_x4(bh4, addr + A_OFF_KH);
                ldsm_x4(bl4, addr + A_OFF_KL);
                mma16816(sc[np*2],   aqh[kc], bh4);
                mma16816(sc[np*2],   aqh[kc], bl4);
                mma16816(sc[np*2],   aql[kc], bh4);
                mma16816(sc[np*2+1], aqh[kc], bh4 + 2);
                mma16816(sc[np*2+1], aqh[kc], bl4 + 2);
                mma16816(sc[np*2+1], aql[kc], bh4 + 2);
            }
        }

        // ---- mask ----
        #pragma unroll
        for (int nt = 0; nt < 8; nt++) {
            int2 mm0 = *(const int2*)(mask + mrow0 + k0 + nt * 8 + cq);
            int2 mm1 = *(const int2*)(mask + mrow1 + k0 + nt * 8 + cq);
            if (mm0.x == 0) sc[nt][0] = -1000000000.0f;
            if (mm0.y == 0) sc[nt][1] = -1000000000.0f;
            if (mm1.x == 0) sc[nt][2] = -1000000000.0f;
            if (mm1.y == 0) sc[nt][3] = -1000000000.0f;
        }

        // ---- online softmax ----
        float mx0 = sc[0][0], mx1 = sc[0][2];
        #pragma unroll
        for (int nt = 0; nt < 8; nt++) {
            mx0 = fmaxf(mx0, fmaxf(sc[nt][0], sc[nt][1]));
            mx1 = fmaxf(mx1, fmaxf(sc[nt][2], sc[nt][3]));
        }
        mx0 = fmaxf(mx0, __shfl_xor_sync(0xffffffff, mx0, 1));
        mx0 = fmaxf(mx0, __shfl_xor_sync(0xffffffff, mx0, 2));
        mx1 = fmaxf(mx1, __shfl_xor_sync(0xffffffff, mx1, 1));
        mx1 = fmaxf(mx1, __shfl_xor_sync(0xffffffff, mx1, 2));

        float mn0 = fmaxf(m0r, mx0), mn1 = fmaxf(m1r, mx1);
        float al0 = __expf(m0r - mn0), al1 = __expf(m1r - mn1);
        m0r = mn0; m1r = mn1;

        float rs0 = 0.0f, rs1 = 0.0f;
        #pragma unroll
        for (int nt = 0; nt < 8; nt++) {
            sc[nt][0] = __expf(sc[nt][0] - mn0); rs0 += sc[nt][0];
            sc[nt][1] = __expf(sc[nt][1] - mn0); rs0 += sc[nt][1];
            sc[nt][2] = __expf(sc[nt][2] - mn1); rs1 += sc[nt][2];
            sc[nt][3] = __expf(sc[nt][3] - mn1); rs1 += sc[nt][3];
        }
        rs0 += __shfl_xor_sync(0xffffffff, rs0, 1);
        rs0 += __shfl_xor_sync(0xffffffff, rs0, 2);
        rs1 += __shfl_xor_sync(0xffffffff, rs1, 1);
        rs1 += __shfl_xor_sync(0xffffffff, rs1, 2);
        l0r = l0r * al0 + rs0;
        l1r = l1r * al1 + rs1;

        #pragma unroll
        for (int nt = 0; nt < 8; nt++) {
            o[nt][0] *= al0; o[nt][1] *= al0;
            o[nt][2] *= al1; o[nt][3] *= al1;
        }

        // ---- pack P into A-fragments (hi/lo) ----
        uint32_t ph[4][4], pl[4][4];
        #pragma unroll
        for (int tp = 0; tp < 4; tp++) {
            pack_split(sc[2*tp][0],   sc[2*tp][1],   ph[tp][0], pl[tp][0]);
            pack_split(sc[2*tp][2],   sc[2*tp][3],   ph[tp][1], pl[tp][1]);
            pack_split(sc[2*tp+1][0], sc[2*tp+1][1], ph[tp][2], pl[tp][2]);
            pack_split(sc[2*tp+1][2], sc[2*tp+1][3], ph[tp][3], pl[tp][3]);
        }

        // ---- O += P V (split-bf16, 3 MMAs), V via ldmatrix.trans ----
        #pragma unroll
        for (int nt2 = 0; nt2 < 4; nt2++) {
            #pragma unroll
            for (int tp = 0; tp < 4; tp++) {
                uint32_t vh4[4], vl4[4];
                uint32_t addr = st + A_OFF_VH + (tp * 16 + v_row) * AROWB
                              + (nt2 * 16 + v_col) * 2;
                ldsm_x4_t(vh4, addr);
                ldsm_x4_t(vl4, addr + (A_OFF_VL - A_OFF_VH));
                mma16816(o[nt2*2],   ph[tp], vh4);
                mma16816(o[nt2*2],   ph[tp], vl4);
                mma16816(o[nt2*2],   pl[tp], vh4);
                mma16816(o[nt2*2+1], ph[tp], vh4 + 2);
                mma16816(o[nt2*2+1], ph[tp], vl4 + 2);
                mma16816(o[nt2*2+1], pl[tp], vh4 + 2);
            }
        }
    }

    // ---- epilogue ----
    float inv0 = 1.0f / l0r, inv1 = 1.0f / l1r;
    size_t row0 = ((size_t)(b * SEQ + q0 + wm + g_)) * DMODEL + h * HDIM;
    #pragma unroll
    for (int nt = 0; nt < 8; nt++) {
        int col = nt * 8 + cq;
        *(float2*)(joint + row0 + col) =
            make_float2(o[nt][0] * inv0, o[nt][1] * inv0);
        *(float2*)(joint + row0 + (size_t)8 * DMODEL + col) =
            make_float2(o[nt][2] * inv1, o[nt][3] * inv1);
    }
}

// ---------------------------------------------------------------------------
extern "C" void kernel_launch(void* const* d_in, const int* in_sizes, int n_in,
                              void* d_out, int out_size)
{
    const float* q    = (const float*)d_in[0];
    const float* k    = (const float*)d_in[1];
    const float* v    = (const float*)d_in[2];
    const int*   mask = (const int*)  d_in[3];
    const float* Wq   = (const float*)d_in[4];
    const float* bq   = (const float*)d_in[5];
    const float* Wk   = (const float*)d_in[6];
    const float* bk   = (const float*)d_in[7];
    const float* Wv   = (const float*)d_in[8];
    const float* bv   = (const float*)d_in[9];
    const float* Wo   = (const float*)d_in[10];
    const float* bo   = (const float*)d_in[11];
    float* out = (float*)d_out;

    void *p_qp, *p_kp, *p_vp, *p_joint, *p_ahi, *p_alo, *p_whi, *p_wlo;
    void *p_qhi, *p_qlo, *p_khi, *p_klo, *p_vhi, *p_vlo;
    cudaGetSymbolAddress(&p_qp, g_qp);
    cudaGetSymbolAddress(&p_kp, g_kp);
    cudaGetSymbolAddress(&p_vp, g_vp);
    cudaGetSymbolAddress(&p_joint, g_joint);
    cudaGetSymbolAddress(&p_ahi, g_ahi);
    cudaGetSymbolAddress(&p_alo, g_alo);
    cudaGetSymbolAddress(&p_whi, g_whi);
    cudaGetSymbolAddress(&p_wlo, g_wlo);
    cudaGetSymbolAddress(&p_qhi, g_qhi);
    cudaGetSymbolAddress(&p_qlo, g_qlo);
    cudaGetSymbolAddress(&p_khi, g_khi);
    cudaGetSymbolAddress(&p_klo, g_klo);
    cudaGetSymbolAddress(&p_vhi, g_vhi);
    cudaGetSymbolAddress(&p_vlo, g_vlo);

    __nv_bfloat16* ahi = (__nv_bfloat16*)p_ahi;
    __nv_bfloat16* alo = (__nv_bfloat16*)p_alo;
    __nv_bfloat16* whi = (__nv_bfloat16*)p_whi;
    __nv_bfloat16* wlo = (__nv_bfloat16*)p_wlo;

    const int nX4 = MTOT * DMODEL / 4;
    const int nW4 = DMODEL * DMODEL / 4;

    cudaFuncSetAttribute(gemm_mma_kernel,
                         cudaFuncAttributeMaxDynamicSharedMemorySize, GEMM_SMEM);
    cudaFuncSetAttribute(attn_mma_kernel,
                         cudaFuncAttributeMaxDynamicSharedMemorySize, ATTN_SMEM);

    dim3 gg(DMODEL / BN, MTOT / BM);

    // projections
    split_kernel<<<nX4 / 256, 256>>>((const float4*)q, (__nv_bfloat162*)ahi, (__nv_bfloat162*)alo, nX4, 1.0f);
    split_kernel<<<nW4 / 256, 256>>>((const float4*)Wq, (__nv_bfloat162*)whi, (__nv_bfloat162*)wlo, nW4, 1.0f);
    gemm_mma_kernel<<<gg, 256, GEMM_SMEM>>>(ahi, alo, whi, wlo, bq, (float*)p_qp);

    split_kernel<<<nX4 / 256, 256>>>((const float4*)k, (__nv_bfloat162*)ahi, (__nv_bfloat162*)alo, nX4, 1.0f);
    split_kernel<<<nW4 / 256, 256>>>((const float4*)Wk, (__nv_bfloat162*)whi, (__nv_bfloat162*)wlo, nW4, 1.0f);
    gemm_mma_kernel<<<gg, 256, GEMM_SMEM>>>(ahi, alo, whi, wlo, bk, (float*)p_kp);

    split_kernel<<<nX4 / 256, 256>>>((const float4*)v, (__nv_bfloat162*)ahi, (__nv_bfloat162*)alo, nX4, 1.0f);
    split_kernel<<<nW4 / 256, 256>>>((const float4*)Wv, (__nv_bfloat162*)whi, (__nv_bfloat162*)wlo, nW4, 1.0f);
    gemm_mma_kernel<<<gg, 256, GEMM_SMEM>>>(ahi, alo, whi, wlo, bv, (float*)p_vp);

    // split projected q/k/v to bf16 hi/lo (scale 1/8 folded into Q)
    split_kernel<<<nX4 / 256, 256>>>((const float4*)p_qp, (__nv_bfloat162*)p_qhi, (__nv_bfloat162*)p_qlo, nX4, 0.125f);
    split_kernel<<<nX4 / 256, 256>>>((const float4*)p_kp, (__nv_bfloat162*)p_khi, (__nv_bfloat162*)p_klo, nX4, 1.0f);
    split_kernel<<<nX4 / 256, 256>>>((const float4*)p_vp, (__nv_bfloat162*)p_vhi, (__nv_bfloat162*)p_vlo, nX4, 1.0f);

    // attention
    dim3 ag(SEQ / 128, NHEADS, BATCH);   // 16 x 16 x 2
    attn_mma_kernel<<<ag, 256, ATTN_SMEM>>>(
        (const __nv_bfloat16*)p_qhi, (const __nv_bfloat16*)p_qlo,
        (const __nv_bfloat16*)p_khi, (const __nv_bfloat16*)p_klo,
        (const __nv_bfloat16*)p_vhi, (const __nv_bfloat16*)p_vlo,
        mask, (float*)p_joint);

    // output projection
    split_kernel<<<nX4 / 256, 256>>>((const float4*)p_joint, (__nv_bfloat162*)ahi, (__nv_bfloat162*)alo, nX4, 1.0f);
    split_kernel<<<nW4 / 256, 256>>>((const float4*)Wo, (__nv_bfloat162*)whi, (__nv_bfloat162*)wlo, nW4, 1.0f);
    gemm_mma_kernel<<<gg, 256, GEMM_SMEM>>>(ahi, alo, whi, wlo, bo, out);
}